// round 8
// baseline (speedup 1.0000x reference)
#include <cuda_runtime.h>
#include <math.h>

#define BSZ 32
#define PP 196
#define ENCD 2048
#define ATTD 512
#define DECD 512
#define VV 10000
#define LL 52
#define TT 51
#define GRID 296

#define OFF_PRED  0L
#define OFF_TOKS  ((long)BSZ*TT*VV)
#define OFF_DLEN  (OFF_TOKS + (long)BSZ*LL)
#define OFF_ALPHA (OFF_DLEN + (long)BSZ)
#define OFF_SORT  (OFF_ALPHA + (long)BSZ*TT*PP)

// ---------------- static device scratch (shrunk for L2 residency) ----------------
__device__ float g_enc[6272L*512];        // 12.8 MB
__device__ float g_pEmb[2L*32*2048];      // 0.5 MB
__device__ float g_pHH[8L*32*2048];       // 2 MB
__device__ float g_pBeta[8L*32*2048];     // 2 MB
__device__ float g_pIH[16L*32*2048];      // 4 MB (also h0/c0 partials [16][32][512])
__device__ float g_mean[32*2048];
__device__ float g_h[32*512];
__device__ float g_c[32*512];
__device__ float g_hnall[1664L*512];
__device__ float g_gates[32*2048];
__device__ float g_betasig[32*2048];
__device__ float g_x2[32*2048];
__device__ float g_alpha[32*196];
__device__ float g_bcomb[2048];
__device__ int   g_sort[32];
__device__ int   g_dlen[32];
__device__ int   g_toks[32*LL];
__device__ unsigned g_barcnt;
__device__ volatile unsigned g_bargen;

__device__ __forceinline__ float sigm(float x) { return 1.f / (1.f + expf(-x)); }

// ---------------- grid-wide software barrier ----------------
__device__ __forceinline__ void gridbar() {
    __syncthreads();
    if (threadIdx.x == 0) {
        __threadfence();
        unsigned gen = g_bargen;
        if (atomicAdd(&g_barcnt, 1u) == GRID - 1) {
            g_barcnt = 0;
            __threadfence();
            g_bargen = gen + 1;
        } else {
            while (g_bargen == gen) { }
        }
        __threadfence();
    }
    __syncthreads();
}

// ---------------- 32-row GEMM partial tile, register-prefetch pipelined ----------------
__device__ void gemm32(const float* __restrict__ X, int ldx,
                       const int* __restrict__ gidx, int gstride,
                       const float* __restrict__ W, int ldw, int wcol0,
                       int Nfull, int nbase, int k0, int klen,
                       float* __restrict__ part, int Nld, float* pool)
{
    float* Xs = pool;                 // 32k x 36
    float* Ws = pool + 1184;          // 32k x 264
    int* roff = (int*)(pool + 1184 + 32*264);
    const int tid = threadIdx.x;
    __syncthreads();
    if (tid < 32) roff[tid] = (gidx ? gidx[tid * gstride] : tid) * ldx;
    __syncthreads();

    const int m0 = (tid >> 5) * 4;
    const int n0 = (tid & 31) * 8;
    const int xm = tid >> 3, xk = (tid & 7) * 4;
    const int wn = tid >> 3, wk = (tid & 7) * 4;

    float acc[4][8];
    #pragma unroll
    for (int i = 0; i < 4; i++)
        #pragma unroll
        for (int j = 0; j < 8; j++) acc[i][j] = 0.f;

    float4 xv = *(const float4*)(X + roff[xm] + k0 + xk);
    float4 wv[8];
    #pragma unroll
    for (int j = 0; j < 8; j++) {
        int ng = nbase + j*32 + wn;
        wv[j] = (ng < Nfull) ? *(const float4*)(W + (long)ng*ldw + wcol0 + k0 + wk)
                             : make_float4(0.f, 0.f, 0.f, 0.f);
    }

    for (int kk = 0; kk < klen; kk += 32) {
        Xs[(xk+0)*36 + xm] = xv.x; Xs[(xk+1)*36 + xm] = xv.y;
        Xs[(xk+2)*36 + xm] = xv.z; Xs[(xk+3)*36 + xm] = xv.w;
        #pragma unroll
        for (int j = 0; j < 8; j++) {
            int n = j*32 + wn;
            Ws[(wk+0)*264 + n] = wv[j].x; Ws[(wk+1)*264 + n] = wv[j].y;
            Ws[(wk+2)*264 + n] = wv[j].z; Ws[(wk+3)*264 + n] = wv[j].w;
        }
        __syncthreads();
        if (kk + 32 < klen) {
            int kc = k0 + kk + 32;
            xv = *(const float4*)(X + roff[xm] + kc + xk);
            #pragma unroll
            for (int j = 0; j < 8; j++) {
                int ng = nbase + j*32 + wn;
                wv[j] = (ng < Nfull) ? *(const float4*)(W + (long)ng*ldw + wcol0 + kc + wk)
                                     : make_float4(0.f, 0.f, 0.f, 0.f);
            }
        }
        #pragma unroll
        for (int k = 0; k < 32; k++) {
            float4 a = *(const float4*)&Xs[k*36 + m0];
            float av[4] = {a.x, a.y, a.z, a.w};
            float4 w0 = *(const float4*)&Ws[k*264 + n0];
            float4 w1 = *(const float4*)&Ws[k*264 + n0 + 4];
            float wvv[8] = {w0.x,w0.y,w0.z,w0.w,w1.x,w1.y,w1.z,w1.w};
            #pragma unroll
            for (int i = 0; i < 4; i++)
                #pragma unroll
                for (int j = 0; j < 8; j++)
                    acc[i][j] = fmaf(av[i], wvv[j], acc[i][j]);
        }
        __syncthreads();
    }
    #pragma unroll
    for (int i = 0; i < 4; i++)
        #pragma unroll
        for (int j = 0; j < 8; j++)
            part[(long)(m0+i)*Nld + nbase + n0 + j] = acc[i][j];
}

// ---------------- 128x64 dense tile, K=2048, pipelined: enc_att ----------------
__device__ void enc_task(int tm, int tn, const float* __restrict__ img,
                         const float* __restrict__ W_enc, const float* __restrict__ b_enc,
                         float* pool)
{
    float* As = pool;
    float* Bs = pool + 4224;
    int* rowb = (int*)(pool + 6400);
    const int tid = threadIdx.x;
    __syncthreads();
    if (tid < 128) {
        int rr = tm*128 + tid;
        int b = rr / PP, p = rr - b*PP;
        rowb[tid] = (g_sort[b]*PP + p) * ENCD;
    }
    __syncthreads();
    float acc[8][4];
    #pragma unroll
    for (int i = 0; i < 8; i++)
        #pragma unroll
        for (int j = 0; j < 4; j++) acc[i][j] = 0.f;
    const int ty = tid >> 4, tx = tid & 15;
    const int m0 = ty*8, n0 = tx*4;
    const int am = tid >> 3, ak = (tid & 7) * 4;
    const int bn = tid >> 3, bk = (tid & 7) * 4;

    float4 av4[4], bv4[2];
    #pragma unroll
    for (int j = 0; j < 4; j++)
        av4[j] = *(const float4*)(img + rowb[j*32 + am] + ak);
    #pragma unroll
    for (int j = 0; j < 2; j++)
        bv4[j] = *(const float4*)(W_enc + (long)(tn*64 + j*32 + bn)*ENCD + bk);

    for (int kc = 0; kc < ENCD; kc += 32) {
        #pragma unroll
        for (int j = 0; j < 4; j++) {
            int m = j*32 + am;
            As[(ak+0)*132+m] = av4[j].x; As[(ak+1)*132+m] = av4[j].y;
            As[(ak+2)*132+m] = av4[j].z; As[(ak+3)*132+m] = av4[j].w;
        }
        #pragma unroll
        for (int j = 0; j < 2; j++) {
            int n = j*32 + bn;
            Bs[(bk+0)*68+n] = bv4[j].x; Bs[(bk+1)*68+n] = bv4[j].y;
            Bs[(bk+2)*68+n] = bv4[j].z; Bs[(bk+3)*68+n] = bv4[j].w;
        }
        __syncthreads();
        if (kc + 32 < ENCD) {
            #pragma unroll
            for (int j = 0; j < 4; j++)
                av4[j] = *(const float4*)(img + rowb[j*32 + am] + kc + 32 + ak);
            #pragma unroll
            for (int j = 0; j < 2; j++)
                bv4[j] = *(const float4*)(W_enc + (long)(tn*64 + j*32 + bn)*ENCD + kc + 32 + bk);
        }
        #pragma unroll
        for (int k = 0; k < 32; k++) {
            float4 a0 = *(const float4*)&As[k*132 + m0];
            float4 a1 = *(const float4*)&As[k*132 + m0 + 4];
            float4 b0 = *(const float4*)&Bs[k*68 + n0];
            float avv[8] = {a0.x,a0.y,a0.z,a0.w,a1.x,a1.y,a1.z,a1.w};
            float bvv[4] = {b0.x,b0.y,b0.z,b0.w};
            #pragma unroll
            for (int i = 0; i < 8; i++)
                #pragma unroll
                for (int j = 0; j < 4; j++)
                    acc[i][j] = fmaf(avv[i], bvv[j], acc[i][j]);
        }
        __syncthreads();
    }
    #pragma unroll
    for (int i = 0; i < 8; i++) {
        int row = tm*128 + m0 + i;
        #pragma unroll
        for (int j = 0; j < 4; j++) {
            int col = tn*64 + n0 + j;
            g_enc[(long)row*512 + col] = acc[i][j] + b_enc[col];
        }
    }
}

// ---------------- 128x64 dense tile, K=512, pipelined: final FC ----------------
__device__ void fc_task(int tm, int tn,
                        const float* __restrict__ W_fc, const float* __restrict__ b_fc,
                        float* __restrict__ out, float* pool)
{
    float* As = pool;
    float* Bs = pool + 4224;
    const int tid = threadIdx.x;
    __syncthreads();
    float acc[8][4];
    #pragma unroll
    for (int i = 0; i < 8; i++)
        #pragma unroll
        for (int j = 0; j < 4; j++) acc[i][j] = 0.f;
    const int ty = tid >> 4, tx = tid & 15;
    const int m0 = ty*8, n0 = tx*4;
    const int am = tid >> 3, ak = (tid & 7) * 4;
    const int bn = tid >> 3, bk = (tid & 7) * 4;

    float4 av4[4], bv4[2];
    #pragma unroll
    for (int j = 0; j < 4; j++)
        av4[j] = *(const float4*)(g_hnall + (long)(tm*128 + j*32 + am)*512 + ak);
    #pragma unroll
    for (int j = 0; j < 2; j++) {
        int ng = tn*64 + j*32 + bn;
        bv4[j] = (ng < VV) ? *(const float4*)(W_fc + (long)ng*512 + bk)
                           : make_float4(0.f,0.f,0.f,0.f);
    }

    for (int kc = 0; kc < 512; kc += 32) {
        #pragma unroll
        for (int j = 0; j < 4; j++) {
            int m = j*32 + am;
            As[(ak+0)*132+m] = av4[j].x; As[(ak+1)*132+m] = av4[j].y;
            As[(ak+2)*132+m] = av4[j].z; As[(ak+3)*132+m] = av4[j].w;
        }
        #pragma unroll
        for (int j = 0; j < 2; j++) {
            int n = j*32 + bn;
            Bs[(bk+0)*68+n] = bv4[j].x; Bs[(bk+1)*68+n] = bv4[j].y;
            Bs[(bk+2)*68+n] = bv4[j].z; Bs[(bk+3)*68+n] = bv4[j].w;
        }
        __syncthreads();
        if (kc + 32 < 512) {
            #pragma unroll
            for (int j = 0; j < 4; j++)
                av4[j] = *(const float4*)(g_hnall + (long)(tm*128 + j*32 + am)*512 + kc + 32 + ak);
            #pragma unroll
            for (int j = 0; j < 2; j++) {
                int ng = tn*64 + j*32 + bn;
                bv4[j] = (ng < VV) ? *(const float4*)(W_fc + (long)ng*512 + kc + 32 + bk)
                                   : make_float4(0.f,0.f,0.f,0.f);
            }
        }
        #pragma unroll
        for (int k = 0; k < 32; k++) {
            float4 a0 = *(const float4*)&As[k*132 + m0];
            float4 a1 = *(const float4*)&As[k*132 + m0 + 4];
            float4 b0 = *(const float4*)&Bs[k*68 + n0];
            float avv[8] = {a0.x,a0.y,a0.z,a0.w,a1.x,a1.y,a1.z,a1.w};
            float bvv[4] = {b0.x,b0.y,b0.z,b0.w};
            #pragma unroll
            for (int i = 0; i < 8; i++)
                #pragma unroll
                for (int j = 0; j < 4; j++)
                    acc[i][j] = fmaf(avv[i], bvv[j], acc[i][j]);
        }
        __syncthreads();
    }
    #pragma unroll
    for (int i = 0; i < 8; i++) {
        int r = tm*128 + m0 + i;
        if (r < TT*BSZ) {
            int tt = r >> 5, bb = r & 31;
            bool act = tt < g_dlen[bb];
            long obase = OFF_PRED + ((long)bb*TT + tt)*VV;
            #pragma unroll
            for (int j = 0; j < 4; j++) {
                int col = tn*64 + n0 + j;
                if (col < VV) out[obase + col] = act ? (acc[i][j] + b_fc[col]) : 0.f;
            }
        }
    }
}

// ---------------- attention: inline dec_att + scores + softmax ----------------
__device__ void attn_task(int b, int t,
                          const float* __restrict__ W_dec, const float* __restrict__ b_dec,
                          const float* __restrict__ w_full, const float* __restrict__ b_full,
                          float* __restrict__ out, float* pool)
{
    float* hs    = pool;            // 512
    float* dec_s = pool + 512;      // 512
    float* wf    = pool + 1024;     // 512
    float* sc    = pool + 1536;     // 256
    float* red   = pool + 1792;     // 256
    const int tid = threadIdx.x;
    __syncthreads();
    for (int a = tid; a < 512; a += 256) {
        hs[a] = g_h[b*512 + a];
        wf[a] = w_full[a];
    }
    __syncthreads();
    #pragma unroll
    for (int rep = 0; rep < 2; rep++) {
        int a = tid + rep*256;
        const float* wr = W_dec + (long)a*512;
        float s = b_dec[a];
        #pragma unroll 8
        for (int k = 0; k < 512; k += 4) {
            float4 w = *(const float4*)(wr + k);
            s = fmaf(hs[k], w.x, s);
            s = fmaf(hs[k+1], w.y, s);
            s = fmaf(hs[k+2], w.z, s);
            s = fmaf(hs[k+3], w.w, s);
        }
        dec_s[a] = s;
    }
    __syncthreads();
    int wid = tid >> 5, lane = tid & 31;
    float bf = b_full[0];
    for (int p = wid; p < PP; p += 8) {
        const float* er = g_enc + ((long)b*PP + p)*512 + lane*16;
        const float* ds = dec_s + lane*16;
        const float* wl = wf + lane*16;
        float s = 0.f;
        #pragma unroll
        for (int q = 0; q < 4; q++) {
            float4 e = *(const float4*)(er + q*4);
            float4 d = *(const float4*)(ds + q*4);
            float4 w = *(const float4*)(wl + q*4);
            s = fmaf(fmaxf(e.x + d.x, 0.f), w.x, s);
            s = fmaf(fmaxf(e.y + d.y, 0.f), w.y, s);
            s = fmaf(fmaxf(e.z + d.z, 0.f), w.z, s);
            s = fmaf(fmaxf(e.w + d.w, 0.f), w.w, s);
        }
        #pragma unroll
        for (int off = 16; off > 0; off >>= 1) s += __shfl_xor_sync(0xffffffffu, s, off);
        if (lane == 0) sc[p] = s + bf;
    }
    __syncthreads();
    float v = (tid < PP) ? sc[tid] : -3.0e38f;
    red[tid] = v; __syncthreads();
    for (int s2 = 128; s2 > 0; s2 >>= 1) {
        if (tid < s2) red[tid] = fmaxf(red[tid], red[tid + s2]);
        __syncthreads();
    }
    float mx = red[0];
    __syncthreads();
    float ev = (tid < PP) ? expf(sc[tid] - mx) : 0.f;
    red[tid] = ev; __syncthreads();
    for (int s2 = 128; s2 > 0; s2 >>= 1) {
        if (tid < s2) red[tid] += red[tid + s2];
        __syncthreads();
    }
    float inv = 1.f / red[0];
    if (tid < PP) {
        float al = ev * inv;
        g_alpha[b*PP + tid] = al;
        out[OFF_ALPHA + ((long)b*TT + t)*PP + tid] = (t < g_dlen[b]) ? al : 0.f;
    }
}

// ---------------- main persistent kernel ----------------
__global__ void __launch_bounds__(256, 2)
persist(const float* __restrict__ img, const int* __restrict__ toks, const int* __restrict__ lens,
        const float* __restrict__ W_enc, const float* __restrict__ b_enc,
        const float* __restrict__ W_dec, const float* __restrict__ b_dec,
        const float* __restrict__ w_full, const float* __restrict__ b_full,
        const float* __restrict__ emb,
        const float* __restrict__ W_ih, const float* __restrict__ b_ih,
        const float* __restrict__ W_hh, const float* __restrict__ b_hh,
        const float* __restrict__ W_h0, const float* __restrict__ b_h0,
        const float* __restrict__ W_c0, const float* __restrict__ b_c0,
        const float* __restrict__ W_beta, const float* __restrict__ b_beta,
        const float* __restrict__ W_fc, const float* __restrict__ b_fc,
        float* __restrict__ out)
{
    __shared__ __align__(16) float pool[9700];
    const int bid = blockIdx.x;
    const int tid = threadIdx.x;

    // ---- P0 ----
    if (bid == 0) {
        if (tid < BSZ) {
            int li = lens[tid];
            int r = 0;
            for (int j = 0; j < BSZ; j++) {
                int lj = lens[j];
                if (lj > li || (lj == li && j < tid)) r++;
            }
            g_sort[r] = tid;
        }
        __syncthreads();
        if (tid < BSZ) {
            int si = g_sort[tid];
            int dl = lens[si] - 1;
            g_dlen[tid] = dl;
            out[OFF_DLEN + tid] = (float)dl;
            out[OFF_SORT + tid] = (float)si;
        }
        __syncthreads();
        for (int idx = tid; idx < BSZ*LL; idx += 256) {
            int b = idx / LL, l = idx - b*LL;
            int tk = toks[g_sort[b]*LL + l];
            g_toks[idx] = tk;
            out[OFF_TOKS + idx] = (float)tk;
        }
    } else if (bid == 1) {
        for (int i = tid; i < 2048; i += 256) g_bcomb[i] = b_ih[i] + b_hh[i];
    } else if (bid == 2) {
        for (int i = tid; i < 32*512; i += 256) g_hnall[1632L*512 + i] = 0.f;
    }
    gridbar();

    // ---- P1: enc_att (392) | mean (32) ----
    for (int task = bid; task < 424; task += GRID) {
        if (task < 392) {
            enc_task(task >> 3, task & 7, img, W_enc, b_enc, pool);
        } else {
            int b = task - 392;
            __syncthreads();
            long srow = (long)g_sort[b] * PP * ENCD;
            int e0 = tid * 8;
            float a[8] = {0,0,0,0,0,0,0,0};
            #pragma unroll 4
            for (int p = 0; p < PP; p++) {
                const float* r = img + srow + (long)p*ENCD + e0;
                float4 v0 = *(const float4*)r;
                float4 v1 = *(const float4*)(r + 4);
                a[0]+=v0.x; a[1]+=v0.y; a[2]+=v0.z; a[3]+=v0.w;
                a[4]+=v1.x; a[5]+=v1.y; a[6]+=v1.z; a[7]+=v1.w;
            }
            #pragma unroll
            for (int i = 0; i < 8; i++)
                g_mean[b*2048 + e0 + i] = a[i] * (1.f/196.f);
        }
    }
    gridbar();

    // ---- P2: h0/c0 partials (uses pIH[16] as [32][512] slices) ----
    for (int task = bid; task < 32; task += GRID) {
        int half = task >> 4, nt = (task >> 3) & 1, sk = task & 7;
        gemm32(g_mean, 2048, (const int*)0, 0, half ? W_c0 : W_h0, 2048, 0,
               512, nt*256, sk*256, 256, g_pIH + (long)(half*8 + sk)*16384, 512, pool);
    }
    gridbar();

    // ---- P3: reduce h0/c0 ----
    for (int task = bid; task < 32; task += GRID) {
        int b = task;
        for (int j = tid; j < 512; j += 256) {
            float s = b_h0[j], s2 = b_c0[j];
            #pragma unroll
            for (int s8 = 0; s8 < 8; s8++) {
                s  += g_pIH[s8*16384 + b*512 + j];
                s2 += g_pIH[(8+s8)*16384 + b*512 + j];
            }
            g_h[b*512 + j] = s;
            g_c[b*512 + j] = s2;
        }
    }
    gridbar();

    // ---- decode loop ----
    for (int t = 0; t < TT; t++) {
        // Ph1: hh SK8(64) | beta SK8(64) | emb gather SK2(16) = 144
        for (int task = bid; task < 144; task += GRID) {
            if (task < 64) {
                int nt = task >> 3, sk = task & 7;
                gemm32(g_h, 512, (const int*)0, 0, W_hh, 512, 0,
                       2048, nt*256, sk*64, 64, g_pHH + (long)sk*65536, 2048, pool);
            } else if (task < 128) {
                int rid = task - 64, nt = rid >> 3, sk = rid & 7;
                gemm32(g_h, 512, (const int*)0, 0, W_beta, 512, 0,
                       2048, nt*256, sk*64, 64, g_pBeta + (long)sk*65536, 2048, pool);
            } else {
                int rid = task - 128, nt = rid >> 1, sk = rid & 1;
                gemm32(emb, 512, g_toks + t, LL, W_ih, 2560, 0,
                       2048, nt*256, sk*256, 256, g_pEmb + (long)sk*65536, 2048, pool);
            }
        }
        gridbar();

        // Ph2: attn(32, inline dec) | gates-base(32) | beta-sigmoid(64) = 128
        for (int task = bid; task < 128; task += GRID) {
            if (task < 32) {
                attn_task(task, t, W_dec, b_dec, w_full, b_full, out, pool);
            } else if (task < 64) {
                int b = task - 32;
                int c0 = tid * 8;
                float4 s0 = *(const float4*)(g_bcomb + c0);
                float4 s1 = *(const float4*)(g_bcomb + c0 + 4);
                #pragma unroll
                for (int sk = 0; sk < 2; sk++) {
                    float4 p0 = *(const float4*)(g_pEmb + (long)sk*65536 + b*2048 + c0);
                    float4 p1 = *(const float4*)(g_pEmb + (long)sk*65536 + b*2048 + c0 + 4);
                    s0.x+=p0.x; s0.y+=p0.y; s0.z+=p0.z; s0.w+=p0.w;
                    s1.x+=p1.x; s1.y+=p1.y; s1.z+=p1.z; s1.w+=p1.w;
                }
                #pragma unroll
                for (int sk = 0; sk < 8; sk++) {
                    float4 p0 = *(const float4*)(g_pHH + (long)sk*65536 + b*2048 + c0);
                    float4 p1 = *(const float4*)(g_pHH + (long)sk*65536 + b*2048 + c0 + 4);
                    s0.x+=p0.x; s0.y+=p0.y; s0.z+=p0.z; s0.w+=p0.w;
                    s1.x+=p1.x; s1.y+=p1.y; s1.z+=p1.z; s1.w+=p1.w;
                }
                *(float4*)(g_gates + b*2048 + c0) = s0;
                *(float4*)(g_gates + b*2048 + c0 + 4) = s1;
            } else {
                int rid = task - 64;
                int b = rid >> 1, half = rid & 1;
                int c0 = half*1024 + tid*4;
                float4 s = *(const float4*)(b_beta + c0);
                #pragma unroll
                for (int sk = 0; sk < 8; sk++) {
                    float4 p = *(const float4*)(g_pBeta + (long)sk*65536 + b*2048 + c0);
                    s.x+=p.x; s.y+=p.y; s.z+=p.z; s.w+=p.w;
                }
                float4 o;
                o.x = sigm(s.x); o.y = sigm(s.y); o.z = sigm(s.z); o.w = sigm(s.w);
                *(float4*)(g_betasig + b*2048 + c0) = o;
            }
        }
        gridbar();

        // Ph3: awe * gate -> x2 (64 tasks: b x 1024-col halves)
        for (int task = bid; task < 64; task += GRID) {
            int b = task >> 1, ch = task & 1;
            float* al = pool;
            __syncthreads();
            if (tid < PP) al[tid] = g_alpha[b*PP + tid];
            __syncthreads();
            int c0 = ch*1024 + tid*4;
            const float* base = img + ((long)(g_sort[b]*PP))*ENCD + c0;
            float4 s = make_float4(0.f,0.f,0.f,0.f);
            #pragma unroll 4
            for (int p = 0; p < PP; p++) {
                float4 v = *(const float4*)(base + (long)p*ENCD);
                float a = al[p];
                s.x = fmaf(a, v.x, s.x); s.y = fmaf(a, v.y, s.y);
                s.z = fmaf(a, v.z, s.z); s.w = fmaf(a, v.w, s.w);
            }
            float4 g = *(const float4*)(g_betasig + b*2048 + c0);
            s.x *= g.x; s.y *= g.y; s.z *= g.z; s.w *= g.w;
            *(float4*)(g_x2 + b*2048 + c0) = s;
        }
        gridbar();

        // Ph4: x2 @ W_ih[:,512:]^T (128 tasks: 8 ntiles x SK16 k128)
        for (int task = bid; task < 128; task += GRID) {
            int nt = task >> 4, sk = task & 15;
            gemm32(g_x2, 2048, (const int*)0, 0, W_ih, 2560, 512,
                   2048, nt*256, sk*128, 128, g_pIH + (long)sk*65536, 2048, pool);
        }
        gridbar();

        // Ph5: gate reduce + LSTM pointwise (64 tasks)
        for (int task = bid; task < 64; task += GRID) {
            int b = task >> 1, half = task & 1;
            int j = half*256 + tid;
            float gi = g_gates[b*2048 + j];
            float gf = g_gates[b*2048 + j + 512];
            float gg = g_gates[b*2048 + j + 1024];
            float go = g_gates[b*2048 + j + 1536];
            #pragma unroll
            for (int sk = 0; sk < 16; sk++) {
                const float* p = g_pIH + (long)sk*65536 + b*2048;
                gi += p[j]; gf += p[j + 512]; gg += p[j + 1024]; go += p[j + 1536];
            }
            float c = g_c[b*512 + j];
            float cn = sigm(gf)*c + sigm(gi)*tanhf(gg);
            float hn = sigm(go)*tanhf(cn);
            g_hnall[((long)t*32 + b)*512 + j] = hn;
            if (t < g_dlen[b]) { g_c[b*512 + j] = cn; g_h[b*512 + j] = hn; }
        }
        gridbar();
    }

    // ---- epilogue: preds = Hn_all @ W_fc^T + b_fc ----
    for (int task = bid; task < 13*157; task += GRID) {
        int tm = task / 157, tn = task - tm*157;
        fc_task(tm, tn, W_fc, b_fc, out, pool);
    }
}

// ---------------- host launcher ----------------
extern "C" void kernel_launch(void* const* d_in, const int* in_sizes, int n_in,
                              void* d_out, int out_size) {
    persist<<<GRID, 256>>>(
        (const float*)d_in[0],  (const int*)d_in[1],   (const int*)d_in[2],
        (const float*)d_in[3],  (const float*)d_in[4],
        (const float*)d_in[5],  (const float*)d_in[6],
        (const float*)d_in[7],  (const float*)d_in[8],
        (const float*)d_in[9],
        (const float*)d_in[10], (const float*)d_in[11],
        (const float*)d_in[12], (const float*)d_in[13],
        (const float*)d_in[14], (const float*)d_in[15],
        (const float*)d_in[16], (const float*)d_in[17],
        (const float*)d_in[18], (const float*)d_in[19],
        (const float*)d_in[20], (const float*)d_in[21],
        (float*)d_out);
    (void)in_sizes; (void)n_in; (void)out_size;
}

// round 9
// speedup vs baseline: 1.6090x; 1.6090x over previous
#include <cuda_runtime.h>
#include <math.h>

#define BSZ 32
#define PP 196
#define ENCD 2048
#define ATTD 512
#define DECD 512
#define VV 10000
#define LL 52
#define TT 51
#define GRID 296

#define OFF_PRED  0L
#define OFF_TOKS  ((long)BSZ*TT*VV)
#define OFF_DLEN  (OFF_TOKS + (long)BSZ*LL)
#define OFF_ALPHA (OFF_DLEN + (long)BSZ)
#define OFF_SORT  (OFF_ALPHA + (long)BSZ*TT*PP)

// ---------------- static device scratch ----------------
__device__ float g_enc[6272L*512];
__device__ float g_embg[51L*32*2048];
__device__ float g_pDec[8L*32*512];
__device__ float g_pHH[8L*32*2048];
__device__ float g_pBeta[8L*32*2048];
__device__ float g_pIH[32L*32*2048];
__device__ float g_mean[32*2048];
__device__ float g_h[32*512];
__device__ float g_c[32*512];
__device__ float g_hnall[1664L*512];
__device__ float g_gates[32*2048];
__device__ float g_betasig[32*2048];
__device__ float g_x2[32*2048];
__device__ float g_alpha[32*196];
__device__ float g_bcomb[2048];
__device__ int   g_sort[32];
__device__ int   g_dlen[32];
__device__ int   g_act[TT];            // active batch count per step
__device__ int   g_toks[32*LL];
__device__ unsigned g_barcnt;
__device__ volatile unsigned g_bargen;

__device__ __forceinline__ float sigm(float x) { return 1.f / (1.f + expf(-x)); }

// ---------------- grid-wide software barrier (nanosleep backoff) ----------------
__device__ __forceinline__ void gridbar() {
    __syncthreads();
    if (threadIdx.x == 0) {
        __threadfence();
        unsigned gen = g_bargen;
        if (atomicAdd(&g_barcnt, 1u) == GRID - 1) {
            g_barcnt = 0;
            __threadfence();
            g_bargen = gen + 1;
        } else {
            while (g_bargen == gen) { __nanosleep(150); }
        }
        __threadfence();
    }
    __syncthreads();
}

// ---------------- 32-row GEMM partial tile, register-prefetch pipelined ----------------
__device__ void gemm32(const float* __restrict__ X, int ldx,
                       const int* __restrict__ gidx, int gstride,
                       const float* __restrict__ W, int ldw, int wcol0,
                       int Nfull, int nbase, int k0, int klen,
                       float* __restrict__ part, int Nld, float* pool)
{
    float* Xs = pool;                 // 32k x 36
    float* Ws = pool + 1184;          // 32k x 264
    int* roff = (int*)(pool + 1184 + 32*264);
    const int tid = threadIdx.x;
    __syncthreads();
    if (tid < 32) roff[tid] = (gidx ? gidx[tid * gstride] : tid) * ldx;
    __syncthreads();

    const int m0 = (tid >> 5) * 4;
    const int n0 = (tid & 31) * 8;
    const int xm = tid >> 3, xk = (tid & 7) * 4;
    const int wn = tid >> 3, wk = (tid & 7) * 4;

    float acc[4][8];
    #pragma unroll
    for (int i = 0; i < 4; i++)
        #pragma unroll
        for (int j = 0; j < 8; j++) acc[i][j] = 0.f;

    float4 xv = *(const float4*)(X + roff[xm] + k0 + xk);
    float4 wv[8];
    #pragma unroll
    for (int j = 0; j < 8; j++) {
        int ng = nbase + j*32 + wn;
        wv[j] = (ng < Nfull) ? *(const float4*)(W + (long)ng*ldw + wcol0 + k0 + wk)
                             : make_float4(0.f, 0.f, 0.f, 0.f);
    }

    for (int kk = 0; kk < klen; kk += 32) {
        Xs[(xk+0)*36 + xm] = xv.x; Xs[(xk+1)*36 + xm] = xv.y;
        Xs[(xk+2)*36 + xm] = xv.z; Xs[(xk+3)*36 + xm] = xv.w;
        #pragma unroll
        for (int j = 0; j < 8; j++) {
            int n = j*32 + wn;
            Ws[(wk+0)*264 + n] = wv[j].x; Ws[(wk+1)*264 + n] = wv[j].y;
            Ws[(wk+2)*264 + n] = wv[j].z; Ws[(wk+3)*264 + n] = wv[j].w;
        }
        __syncthreads();
        if (kk + 32 < klen) {
            int kc = k0 + kk + 32;
            xv = *(const float4*)(X + roff[xm] + kc + xk);
            #pragma unroll
            for (int j = 0; j < 8; j++) {
                int ng = nbase + j*32 + wn;
                wv[j] = (ng < Nfull) ? *(const float4*)(W + (long)ng*ldw + wcol0 + kc + wk)
                                     : make_float4(0.f, 0.f, 0.f, 0.f);
            }
        }
        #pragma unroll
        for (int k = 0; k < 32; k++) {
            float4 a = *(const float4*)&Xs[k*36 + m0];
            float av[4] = {a.x, a.y, a.z, a.w};
            float4 w0 = *(const float4*)&Ws[k*264 + n0];
            float4 w1 = *(const float4*)&Ws[k*264 + n0 + 4];
            float wvv[8] = {w0.x,w0.y,w0.z,w0.w,w1.x,w1.y,w1.z,w1.w};
            #pragma unroll
            for (int i = 0; i < 4; i++)
                #pragma unroll
                for (int j = 0; j < 8; j++)
                    acc[i][j] = fmaf(av[i], wvv[j], acc[i][j]);
        }
        __syncthreads();
    }
    #pragma unroll
    for (int i = 0; i < 4; i++)
        #pragma unroll
        for (int j = 0; j < 8; j++)
            part[(long)(m0+i)*Nld + nbase + n0 + j] = acc[i][j];
}

// ---------------- 128x64 dense tile, K=2048, pipelined: enc_att ----------------
__device__ void enc_task(int tm, int tn, const float* __restrict__ img,
                         const float* __restrict__ W_enc, const float* __restrict__ b_enc,
                         float* pool)
{
    float* As = pool;
    float* Bs = pool + 4224;
    int* rowb = (int*)(pool + 6400);
    const int tid = threadIdx.x;
    __syncthreads();
    if (tid < 128) {
        int rr = tm*128 + tid;
        int b = rr / PP, p = rr - b*PP;
        rowb[tid] = (g_sort[b]*PP + p) * ENCD;
    }
    __syncthreads();
    float acc[8][4];
    #pragma unroll
    for (int i = 0; i < 8; i++)
        #pragma unroll
        for (int j = 0; j < 4; j++) acc[i][j] = 0.f;
    const int ty = tid >> 4, tx = tid & 15;
    const int m0 = ty*8, n0 = tx*4;
    const int am = tid >> 3, ak = (tid & 7) * 4;
    const int bn = tid >> 3, bk = (tid & 7) * 4;

    float4 av4[4], bv4[2];
    #pragma unroll
    for (int j = 0; j < 4; j++)
        av4[j] = *(const float4*)(img + rowb[j*32 + am] + ak);
    #pragma unroll
    for (int j = 0; j < 2; j++)
        bv4[j] = *(const float4*)(W_enc + (long)(tn*64 + j*32 + bn)*ENCD + bk);

    for (int kc = 0; kc < ENCD; kc += 32) {
        #pragma unroll
        for (int j = 0; j < 4; j++) {
            int m = j*32 + am;
            As[(ak+0)*132+m] = av4[j].x; As[(ak+1)*132+m] = av4[j].y;
            As[(ak+2)*132+m] = av4[j].z; As[(ak+3)*132+m] = av4[j].w;
        }
        #pragma unroll
        for (int j = 0; j < 2; j++) {
            int n = j*32 + bn;
            Bs[(bk+0)*68+n] = bv4[j].x; Bs[(bk+1)*68+n] = bv4[j].y;
            Bs[(bk+2)*68+n] = bv4[j].z; Bs[(bk+3)*68+n] = bv4[j].w;
        }
        __syncthreads();
        if (kc + 32 < ENCD) {
            #pragma unroll
            for (int j = 0; j < 4; j++)
                av4[j] = *(const float4*)(img + rowb[j*32 + am] + kc + 32 + ak);
            #pragma unroll
            for (int j = 0; j < 2; j++)
                bv4[j] = *(const float4*)(W_enc + (long)(tn*64 + j*32 + bn)*ENCD + kc + 32 + bk);
        }
        #pragma unroll
        for (int k = 0; k < 32; k++) {
            float4 a0 = *(const float4*)&As[k*132 + m0];
            float4 a1 = *(const float4*)&As[k*132 + m0 + 4];
            float4 b0 = *(const float4*)&Bs[k*68 + n0];
            float avv[8] = {a0.x,a0.y,a0.z,a0.w,a1.x,a1.y,a1.z,a1.w};
            float bvv[4] = {b0.x,b0.y,b0.z,b0.w};
            #pragma unroll
            for (int i = 0; i < 8; i++)
                #pragma unroll
                for (int j = 0; j < 4; j++)
                    acc[i][j] = fmaf(avv[i], bvv[j], acc[i][j]);
        }
        __syncthreads();
    }
    #pragma unroll
    for (int i = 0; i < 8; i++) {
        int row = tm*128 + m0 + i;
        #pragma unroll
        for (int j = 0; j < 4; j++) {
            int col = tn*64 + n0 + j;
            g_enc[(long)row*512 + col] = acc[i][j] + b_enc[col];
        }
    }
}

// ---------------- 128x64 dense tile, K=512, pipelined: final FC ----------------
__device__ void fc_task(int tm, int tn,
                        const float* __restrict__ W_fc, const float* __restrict__ b_fc,
                        float* __restrict__ out, float* pool)
{
    float* As = pool;
    float* Bs = pool + 4224;
    const int tid = threadIdx.x;
    __syncthreads();
    float acc[8][4];
    #pragma unroll
    for (int i = 0; i < 8; i++)
        #pragma unroll
        for (int j = 0; j < 4; j++) acc[i][j] = 0.f;
    const int ty = tid >> 4, tx = tid & 15;
    const int m0 = ty*8, n0 = tx*4;
    const int am = tid >> 3, ak = (tid & 7) * 4;
    const int bn = tid >> 3, bk = (tid & 7) * 4;

    float4 av4[4], bv4[2];
    #pragma unroll
    for (int j = 0; j < 4; j++)
        av4[j] = *(const float4*)(g_hnall + (long)(tm*128 + j*32 + am)*512 + ak);
    #pragma unroll
    for (int j = 0; j < 2; j++) {
        int ng = tn*64 + j*32 + bn;
        bv4[j] = (ng < VV) ? *(const float4*)(W_fc + (long)ng*512 + bk)
                           : make_float4(0.f,0.f,0.f,0.f);
    }

    for (int kc = 0; kc < 512; kc += 32) {
        #pragma unroll
        for (int j = 0; j < 4; j++) {
            int m = j*32 + am;
            As[(ak+0)*132+m] = av4[j].x; As[(ak+1)*132+m] = av4[j].y;
            As[(ak+2)*132+m] = av4[j].z; As[(ak+3)*132+m] = av4[j].w;
        }
        #pragma unroll
        for (int j = 0; j < 2; j++) {
            int n = j*32 + bn;
            Bs[(bk+0)*68+n] = bv4[j].x; Bs[(bk+1)*68+n] = bv4[j].y;
            Bs[(bk+2)*68+n] = bv4[j].z; Bs[(bk+3)*68+n] = bv4[j].w;
        }
        __syncthreads();
        if (kc + 32 < 512) {
            #pragma unroll
            for (int j = 0; j < 4; j++)
                av4[j] = *(const float4*)(g_hnall + (long)(tm*128 + j*32 + am)*512 + kc + 32 + ak);
            #pragma unroll
            for (int j = 0; j < 2; j++) {
                int ng = tn*64 + j*32 + bn;
                bv4[j] = (ng < VV) ? *(const float4*)(W_fc + (long)ng*512 + kc + 32 + bk)
                                   : make_float4(0.f,0.f,0.f,0.f);
            }
        }
        #pragma unroll
        for (int k = 0; k < 32; k++) {
            float4 a0 = *(const float4*)&As[k*132 + m0];
            float4 a1 = *(const float4*)&As[k*132 + m0 + 4];
            float4 b0 = *(const float4*)&Bs[k*68 + n0];
            float avv[8] = {a0.x,a0.y,a0.z,a0.w,a1.x,a1.y,a1.z,a1.w};
            float bvv[4] = {b0.x,b0.y,b0.z,b0.w};
            #pragma unroll
            for (int i = 0; i < 8; i++)
                #pragma unroll
                for (int j = 0; j < 4; j++)
                    acc[i][j] = fmaf(avv[i], bvv[j], acc[i][j]);
        }
        __syncthreads();
    }
    #pragma unroll
    for (int i = 0; i < 8; i++) {
        int r = tm*128 + m0 + i;
        if (r < TT*BSZ) {
            int tt = r >> 5, bb = r & 31;
            bool act = tt < g_dlen[bb];
            long obase = OFF_PRED + ((long)bb*TT + tt)*VV;
            #pragma unroll
            for (int j = 0; j < 4; j++) {
                int col = tn*64 + n0 + j;
                if (col < VV) out[obase + col] = act ? (acc[i][j] + b_fc[col]) : 0.f;
            }
        }
    }
}

// ---------------- attention: reduce pDec + scores + softmax ----------------
__device__ void attn_task(int b, int t, const float* __restrict__ b_dec,
                          const float* __restrict__ w_full, const float* __restrict__ b_full,
                          float* __restrict__ out, float* pool)
{
    float* dec_s = pool;
    float* wf    = pool + 512;
    float* sc    = pool + 1024;
    float* red   = pool + 1280;
    const int tid = threadIdx.x;
    __syncthreads();
    for (int a = tid; a < 512; a += 256) {
        float s = b_dec[a];
        #pragma unroll
        for (int sk = 0; sk < 8; sk++) s += g_pDec[sk*16384 + b*512 + a];
        dec_s[a] = s;
        wf[a] = w_full[a];
    }
    __syncthreads();
    int wid = tid >> 5, lane = tid & 31;
    float bf = b_full[0];
    for (int p = wid; p < PP; p += 8) {
        const float* er = g_enc + ((long)b*PP + p)*512 + lane*16;
        const float* ds = dec_s + lane*16;
        const float* wl = wf + lane*16;
        float s = 0.f;
        #pragma unroll
        for (int q = 0; q < 4; q++) {
            float4 e = *(const float4*)(er + q*4);
            float4 d = *(const float4*)(ds + q*4);
            float4 w = *(const float4*)(wl + q*4);
            s = fmaf(fmaxf(e.x + d.x, 0.f), w.x, s);
            s = fmaf(fmaxf(e.y + d.y, 0.f), w.y, s);
            s = fmaf(fmaxf(e.z + d.z, 0.f), w.z, s);
            s = fmaf(fmaxf(e.w + d.w, 0.f), w.w, s);
        }
        #pragma unroll
        for (int off = 16; off > 0; off >>= 1) s += __shfl_xor_sync(0xffffffffu, s, off);
        if (lane == 0) sc[p] = s + bf;
    }
    __syncthreads();
    float v = (tid < PP) ? sc[tid] : -3.0e38f;
    red[tid] = v; __syncthreads();
    for (int s2 = 128; s2 > 0; s2 >>= 1) {
        if (tid < s2) red[tid] = fmaxf(red[tid], red[tid + s2]);
        __syncthreads();
    }
    float mx = red[0];
    __syncthreads();
    float ev = (tid < PP) ? expf(sc[tid] - mx) : 0.f;
    red[tid] = ev; __syncthreads();
    for (int s2 = 128; s2 > 0; s2 >>= 1) {
        if (tid < s2) red[tid] += red[tid + s2];
        __syncthreads();
    }
    float inv = 1.f / red[0];
    if (tid < PP) {
        float al = ev * inv;
        g_alpha[b*PP + tid] = al;
        out[OFF_ALPHA + ((long)b*TT + t)*PP + tid] = al;   // caller guarantees active
    }
}

// ---------------- main persistent kernel ----------------
__global__ void __launch_bounds__(256, 2)
persist(const float* __restrict__ img, const int* __restrict__ toks, const int* __restrict__ lens,
        const float* __restrict__ W_enc, const float* __restrict__ b_enc,
        const float* __restrict__ W_dec, const float* __restrict__ b_dec,
        const float* __restrict__ w_full, const float* __restrict__ b_full,
        const float* __restrict__ emb,
        const float* __restrict__ W_ih, const float* __restrict__ b_ih,
        const float* __restrict__ W_hh, const float* __restrict__ b_hh,
        const float* __restrict__ W_h0, const float* __restrict__ b_h0,
        const float* __restrict__ W_c0, const float* __restrict__ b_c0,
        const float* __restrict__ W_beta, const float* __restrict__ b_beta,
        const float* __restrict__ W_fc, const float* __restrict__ b_fc,
        float* __restrict__ out)
{
    __shared__ __align__(16) float pool[9700];
    const int bid = blockIdx.x;
    const int tid = threadIdx.x;

    // ---- P0 ----
    if (bid == 0) {
        if (tid < BSZ) {
            int li = lens[tid];
            int r = 0;
            for (int j = 0; j < BSZ; j++) {
                int lj = lens[j];
                if (lj > li || (lj == li && j < tid)) r++;
            }
            g_sort[r] = tid;
        }
        __syncthreads();
        if (tid < BSZ) {
            int si = g_sort[tid];
            int dl = lens[si] - 1;
            g_dlen[tid] = dl;
            out[OFF_DLEN + tid] = (float)dl;
            out[OFF_SORT + tid] = (float)si;
        }
        __syncthreads();
        if (tid < TT) {                 // active count per step
            int a = 0;
            for (int j = 0; j < BSZ; j++) a += (g_dlen[j] > tid) ? 1 : 0;
            g_act[tid] = a;
        }
        for (int idx = tid; idx < BSZ*LL; idx += 256) {
            int b = idx / LL, l = idx - b*LL;
            int tk = toks[g_sort[b]*LL + l];
            g_toks[idx] = tk;
            out[OFF_TOKS + idx] = (float)tk;
        }
    } else if (bid == 1) {
        for (int i = tid; i < 2048; i += 256) g_bcomb[i] = b_ih[i] + b_hh[i];
    } else if (bid == 2) {
        for (int i = tid; i < 32*512; i += 256) g_hnall[1632L*512 + i] = 0.f;
    }
    gridbar();

    // ---- P1: enc_att (392) | embg (408) | mean (32) ----
    for (int task = bid; task < 832; task += GRID) {
        if (task < 392) {
            enc_task(task >> 3, task & 7, img, W_enc, b_enc, pool);
        } else if (task < 800) {
            int id = task - 392;
            int tt = id >> 3, nt = id & 7;
            gemm32(emb, 512, g_toks + tt, LL, W_ih, 2560, 0,
                   2048, nt*256, 0, 512, g_embg + (long)tt*65536, 2048, pool);
        } else {
            int b = task - 800;
            __syncthreads();
            long srow = (long)g_sort[b] * PP * ENCD;
            int e0 = tid * 8;
            float a[8] = {0,0,0,0,0,0,0,0};
            #pragma unroll 4
            for (int p = 0; p < PP; p++) {
                const float* r = img + srow + (long)p*ENCD + e0;
                float4 v0 = *(const float4*)r;
                float4 v1 = *(const float4*)(r + 4);
                a[0]+=v0.x; a[1]+=v0.y; a[2]+=v0.z; a[3]+=v0.w;
                a[4]+=v1.x; a[5]+=v1.y; a[6]+=v1.z; a[7]+=v1.w;
            }
            #pragma unroll
            for (int i = 0; i < 8; i++)
                g_mean[b*2048 + e0 + i] = a[i] * (1.f/196.f);
        }
    }
    gridbar();

    // ---- P2: h0/c0 partials ----
    for (int task = bid; task < 32; task += GRID) {
        int half = task >> 4, nt = (task >> 3) & 1, sk = task & 7;
        gemm32(g_mean, 2048, (const int*)0, 0, half ? W_c0 : W_h0, 2048, 0,
               512, nt*256, sk*256, 256, g_pIH + (long)(half*8 + sk)*16384, 512, pool);
    }
    gridbar();

    // ---- P3: reduce h0/c0 ----
    for (int task = bid; task < 32; task += GRID) {
        int b = task;
        for (int j = tid; j < 512; j += 256) {
            float s = b_h0[j], s2 = b_c0[j];
            #pragma unroll
            for (int s8 = 0; s8 < 8; s8++) {
                s  += g_pIH[s8*16384 + b*512 + j];
                s2 += g_pIH[(8+s8)*16384 + b*512 + j];
            }
            g_h[b*512 + j] = s;
            g_c[b*512 + j] = s2;
        }
    }
    gridbar();

    // ---- decode loop (R7 structure + active-prefix skipping) ----
    for (int t = 0; t < TT; t++) {
        const int A = g_act[t];        // active batches this step (prefix [0,A))

        // Ph1: dec(16) | hh(64) | beta(64)
        for (int task = bid; task < 144; task += GRID) {
            if (task < 16) {
                int nt = task >> 3, sk = task & 7;
                gemm32(g_h, 512, (const int*)0, 0, W_dec, 512, 0,
                       512, nt*256, sk*64, 64, g_pDec + (long)sk*16384, 512, pool);
            } else if (task < 80) {
                int rid = task - 16, nt = rid >> 3, sk = rid & 7;
                gemm32(g_h, 512, (const int*)0, 0, W_hh, 512, 0,
                       2048, nt*256, sk*64, 64, g_pHH + (long)sk*65536, 2048, pool);
            } else {
                int rid = task - 80, nt = rid >> 3, sk = rid & 7;
                gemm32(g_h, 512, (const int*)0, 0, W_beta, 512, 0,
                       2048, nt*256, sk*64, 64, g_pBeta + (long)sk*65536, 2048, pool);
            }
        }
        gridbar();

        // Ph2: attn(32) | gates-base(32) | beta-sigmoid(64) — skip frozen b
        for (int task = bid; task < 128; task += GRID) {
            if (task < 32) {
                int b = task;
                if (b < A) {
                    attn_task(b, t, b_dec, w_full, b_full, out, pool);
                } else if (tid < PP) {
                    out[OFF_ALPHA + ((long)b*TT + t)*PP + tid] = 0.f;
                }
            } else if (task < 64) {
                int b = task - 32;
                if (b >= A) continue;
                int c0 = tid * 8;
                float4 s0 = *(const float4*)(g_bcomb + c0);
                float4 s1 = *(const float4*)(g_bcomb + c0 + 4);
                float4 e0 = *(const float4*)(g_embg + (long)t*65536 + b*2048 + c0);
                float4 e1 = *(const float4*)(g_embg + (long)t*65536 + b*2048 + c0 + 4);
                s0.x+=e0.x; s0.y+=e0.y; s0.z+=e0.z; s0.w+=e0.w;
                s1.x+=e1.x; s1.y+=e1.y; s1.z+=e1.z; s1.w+=e1.w;
                #pragma unroll
                for (int sk = 0; sk < 8; sk++) {
                    float4 p0 = *(const float4*)(g_pHH + (long)sk*65536 + b*2048 + c0);
                    float4 p1 = *(const float4*)(g_pHH + (long)sk*65536 + b*2048 + c0 + 4);
                    s0.x+=p0.x; s0.y+=p0.y; s0.z+=p0.z; s0.w+=p0.w;
                    s1.x+=p1.x; s1.y+=p1.y; s1.z+=p1.z; s1.w+=p1.w;
                }
                *(float4*)(g_gates + b*2048 + c0) = s0;
                *(float4*)(g_gates + b*2048 + c0 + 4) = s1;
            } else {
                int rid = task - 64;
                int b = rid >> 1, half = rid & 1;
                if (b >= A) continue;
                int c0 = half*1024 + tid*4;
                float4 s = *(const float4*)(b_beta + c0);
                #pragma unroll
                for (int sk = 0; sk < 8; sk++) {
                    float4 p = *(const float4*)(g_pBeta + (long)sk*65536 + b*2048 + c0);
                    s.x+=p.x; s.y+=p.y; s.z+=p.z; s.w+=p.w;
                }
                float4 o;
                o.x = sigm(s.x); o.y = sigm(s.y); o.z = sigm(s.z); o.w = sigm(s.w);
                *(float4*)(g_betasig + b*2048 + c0) = o;
            }
        }
        gridbar();

        // Ph3: awe * gate -> x2 — only active b (the big img DRAM scan)
        for (int task = bid; task < 64; task += GRID) {
            int b = task >> 1, ch = task & 1;
            if (b >= A) continue;
            float* al = pool;
            __syncthreads();
            if (tid < PP) al[tid] = g_alpha[b*PP + tid];
            __syncthreads();
            int c0 = ch*1024 + tid*4;
            const float* base = img + ((long)(g_sort[b]*PP))*ENCD + c0;
            float4 s = make_float4(0.f,0.f,0.f,0.f);
            #pragma unroll 4
            for (int p = 0; p < PP; p++) {
                float4 v = *(const float4*)(base + (long)p*ENCD);
                float a = al[p];
                s.x = fmaf(a, v.x, s.x); s.y = fmaf(a, v.y, s.y);
                s.z = fmaf(a, v.z, s.z); s.w = fmaf(a, v.w, s.w);
            }
            float4 g = *(const float4*)(g_betasig + b*2048 + c0);
            s.x *= g.x; s.y *= g.y; s.z *= g.z; s.w *= g.w;
            *(float4*)(g_x2 + b*2048 + c0) = s;
        }
        gridbar();

        // Ph4: x2 @ W_ih[:,512:]^T (256 tasks: 8 ntiles x SK32 k64)
        for (int task = bid; task < 256; task += GRID) {
            int nt = task >> 5, sk = task & 31;
            gemm32(g_x2, 2048, (const int*)0, 0, W_ih, 2560, 512,
                   2048, nt*256, sk*64, 64, g_pIH + (long)sk*65536, 2048, pool);
        }
        gridbar();

        // Ph5: gate reduce + LSTM pointwise — only active b
        for (int task = bid; task < 64; task += GRID) {
            int b = task >> 1, half = task & 1;
            if (b >= A) continue;
            int j = half*256 + tid;
            float gi = g_gates[b*2048 + j];
            float gf = g_gates[b*2048 + j + 512];
            float gg = g_gates[b*2048 + j + 1024];
            float go = g_gates[b*2048 + j + 1536];
            #pragma unroll
            for (int sk = 0; sk < 32; sk++) {
                const float* p = g_pIH + (long)sk*65536 + b*2048;
                gi += p[j]; gf += p[j + 512]; gg += p[j + 1024]; go += p[j + 1536];
            }
            float c = g_c[b*512 + j];
            float cn = sigm(gf)*c + sigm(gi)*tanhf(gg);
            float hn = sigm(go)*tanhf(cn);
            g_hnall[((long)t*32 + b)*512 + j] = hn;
            g_c[b*512 + j] = cn;
            g_h[b*512 + j] = hn;
        }
        gridbar();
    }

    // ---- epilogue: preds = Hn_all @ W_fc^T + b_fc ----
    for (int task = bid; task < 13*157; task += GRID) {
        int tm = task / 157, tn = task - tm*157;
        fc_task(tm, tn, W_fc, b_fc, out, pool);
    }
}

// ---------------- host launcher ----------------
extern "C" void kernel_launch(void* const* d_in, const int* in_sizes, int n_in,
                              void* d_out, int out_size) {
    persist<<<GRID, 256>>>(
        (const float*)d_in[0],  (const int*)d_in[1],   (const int*)d_in[2],
        (const float*)d_in[3],  (const float*)d_in[4],
        (const float*)d_in[5],  (const float*)d_in[6],
        (const float*)d_in[7],  (const float*)d_in[8],
        (const float*)d_in[9],
        (const float*)d_in[10], (const float*)d_in[11],
        (const float*)d_in[12], (const float*)d_in[13],
        (const float*)d_in[14], (const float*)d_in[15],
        (const float*)d_in[16], (const float*)d_in[17],
        (const float*)d_in[18], (const float*)d_in[19],
        (const float*)d_in[20], (const float*)d_in[21],
        (float*)d_out);
    (void)in_sizes; (void)n_in; (void)out_size;
}